// round 3
// baseline (speedup 1.0000x reference)
#include <cuda_runtime.h>
#include <math.h>

#define BDIM 8
#define FDIM 1025
#define MDIM 8
#define TDIM 512
#define NBF (BDIM * FDIM)            // 8200
#define NTHREADS 288
#define XS 516                        // padded SMEM row stride (bank-conflict-free)

#define QELEMS (NBF * MDIM * MDIM)           // 524,800  (Q stored as real part only)
#define XTCOUNT (NBF * MDIM * TDIM)          // 33,587,200
#define PER_B_XT (FDIM * MDIM * TDIM)        // 4,198,400
#define PER_B_QE (FDIM * MDIM * MDIM)        // 65,600

// SMEM layout (float offsets)
#define OFF_SXR 0
#define OFF_SXI (OFF_SXR + MDIM * XS)        // 4128
#define OFF_SR  (OFF_SXI + MDIM * XS)        // 8256
#define OFF_V   (OFF_SR + MDIM * XS)         // 12384  (512 float2)
#define OFF_PART (OFF_V + 1024)              // 13408  (2304 float2)
#define OFF_SQ  (OFF_PART + 4608)            // 18016  (64 float2)
#define OFF_QB  (OFF_SQ + 128)               // 18144  (8 float2)
#define OFF_VQ  (OFF_QB + 16)                // 18160  (64 float2)
#define OFF_VB  (OFF_VQ + 128)               // 18288  (8 float2)
#define OFF_RED (OFF_VB + 16)                // 18304  (288 float)
#define SMEM_FLOATS (OFF_RED + NTHREADS)
#define SMEM_BYTES (SMEM_FLOATS * 4)

__device__ float g_partial[NBF];
__device__ float g_xtscale[BDIM];
__device__ float g_qscale[BDIM];

__constant__ unsigned char c_pm[36] = {
    0,0,0,0,0,0,0,0,
    1,1,1,1,1,1,1,
    2,2,2,2,2,2,
    3,3,3,3,3,
    4,4,4,4,
    5,5,5,
    6,6,
    7};
__constant__ unsigned char c_pn[36] = {
    0,1,2,3,4,5,6,7,
    1,2,3,4,5,6,7,
    2,3,4,5,6,7,
    3,4,5,6,7,
    4,5,6,7,
    5,6,7,
    6,7,
    7};

__global__ __launch_bounds__(NTHREADS)
void iss_main(const float* __restrict__ r,
              const float* __restrict__ Qr,
              const float* __restrict__ Qi,
              const float* __restrict__ xr,
              const float* __restrict__ xi,
              float* __restrict__ out)
{
    extern __shared__ float sm[];
    float*  sxr  = sm + OFF_SXR;
    float*  sxi  = sm + OFF_SXI;
    float*  sr   = sm + OFF_SR;
    float2* V    = (float2*)(sm + OFF_V);     // [k][m][n]
    float2* part = (float2*)(sm + OFF_PART);  // [pair][k][chunk]
    float2* sQ   = (float2*)(sm + OFF_SQ);    // [k][m]
    float2* qb   = (float2*)(sm + OFF_QB);
    float2* Vq   = (float2*)(sm + OFF_VQ);
    float2* vb   = (float2*)(sm + OFF_VB);
    float*  red  = sm + OFF_RED;

    const int tid = threadIdx.x;
    const int bf = blockIdx.x;
    const size_t base = (size_t)bf * (MDIM * TDIM);

    // ---- stage inputs in SMEM (r clipped at load) ----
    for (int i = tid; i < MDIM * TDIM; i += NTHREADS) {
        int m = i >> 9, t = i & 511;
        sxr[m * XS + t] = xr[base + i];
        sxi[m * XS + t] = xi[base + i];
        sr [m * XS + t] = fmaxf(r[base + i], 1e-3f);
    }
    if (tid < 64) {
        sQ[tid] = make_float2(Qr[(size_t)bf * 64 + tid], Qi[(size_t)bf * 64 + tid]);
    }
    __syncthreads();

    // ---- V[k,m,n] = (1/T) sum_t clip(r)[k,t] * x[m,t] * conj(x[n,t]) ----
    {
        int chunk = tid / 36;
        int pair  = tid - chunk * 36;
        int m = c_pm[pair], n = c_pn[pair];
        const float* pxrm = sxr + m * XS;
        const float* pxim = sxi + m * XS;
        const float* pxrn = sxr + n * XS;
        const float* pxin = sxi + n * XS;
        float2 acc[8];
        #pragma unroll
        for (int k = 0; k < 8; k++) acc[k] = make_float2(0.f, 0.f);
        const int t0 = chunk * 64;
        #pragma unroll 4
        for (int tt = 0; tt < 64; tt++) {
            int t = t0 + tt;
            float xrm = pxrm[t], ximv = pxim[t];
            float xrn = pxrn[t], xinv = pxin[t];
            float a  = xrm * xrn + ximv * xinv;   // Re(x_m conj(x_n))
            float bb = ximv * xrn - xrm * xinv;   // Im(x_m conj(x_n))
            #pragma unroll
            for (int k = 0; k < 8; k++) {
                float rv = sr[k * XS + t];
                acc[k].x = fmaf(rv, a,  acc[k].x);
                acc[k].y = fmaf(rv, bb, acc[k].y);
            }
        }
        #pragma unroll
        for (int k = 0; k < 8; k++)
            part[(pair * 8 + k) * 8 + chunk] = acc[k];
    }
    __syncthreads();

    // reduce over chunks, Hermitian fill. 36*8 = 288 items exactly.
    {
        int pair = tid >> 3, k = tid & 7;
        int m = c_pm[pair], n = c_pn[pair];
        float2 s = make_float2(0.f, 0.f);
        #pragma unroll
        for (int c = 0; c < 8; c++) {
            float2 p = part[(pair * 8 + k) * 8 + c];
            s.x += p.x; s.y += p.y;
        }
        s.x *= (1.0f / TDIM);
        s.y *= (1.0f / TDIM);
        V[(k * 8 + m) * 8 + n] = s;
        V[(k * 8 + n) * 8 + m] = make_float2(s.x, -s.y);
    }
    __syncthreads();

    // trV + diagonal regularization
    if (tid < 8) {
        int k = tid;
        float tr = 0.f;
        #pragma unroll
        for (int m = 0; m < 8; m++) tr += V[(k * 8 + m) * 8 + m].x;
        float reg = fmaxf(tr, 1.0f) * 1e-6f;
        #pragma unroll
        for (int m = 0; m < 8; m++) V[(k * 8 + m) * 8 + m].x += reg;
    }
    __syncthreads();

    // ---- 2 x 8 sweep iteration, done by warp 0 ----
    if (tid < 32) {
        const int lane = tid;
        for (int it = 0; it < 2; it++) {
            for (int k = 0; k < 8; k++) {
                if (lane < 8) qb[lane] = sQ[k * 8 + lane];
                __syncwarp();
                // Vq[kp,m] = sum_n V[kp,m,n] * conj(q[n])
                #pragma unroll
                for (int rep = 0; rep < 2; rep++) {
                    int kp = (lane >> 3) + rep * 4;
                    int m  = lane & 7;
                    float sx = 0.f, sy = 0.f;
                    #pragma unroll
                    for (int n = 0; n < 8; n++) {
                        float2 vv = V[(kp * 8 + m) * 8 + n];
                        float2 qq = qb[n];
                        sx += vv.x * qq.x + vv.y * qq.y;
                        sy += vv.y * qq.x - vv.x * qq.y;
                    }
                    Vq[kp * 8 + m] = make_float2(sx, sy);
                }
                __syncwarp();
                if (lane < 8) {
                    int kp = lane;
                    float sreal = 0.f;
                    float2 num = make_float2(0.f, 0.f);
                    #pragma unroll
                    for (int m = 0; m < 8; m++) {
                        float2 qq  = qb[m];
                        float2 vqm = Vq[kp * 8 + m];
                        sreal += qq.x * vqm.x - qq.y * vqm.y;
                        float2 Qv = sQ[kp * 8 + m];
                        num.x += Qv.x * vqm.x - Qv.y * vqm.y;
                        num.y += Qv.x * vqm.y + Qv.y * vqm.x;
                    }
                    float qv = fmaxf(sreal, 1e-6f);
                    float2 vv;
                    if (kp == k) {
                        vv = make_float2(1.0f - 1.0f / sqrtf(qv), 0.0f);
                    } else {
                        vv = make_float2(num.x / qv, num.y / qv);
                    }
                    vb[kp] = vv;
                }
                __syncwarp();
                // Q[kp,m] -= v[kp] * q[m]
                #pragma unroll
                for (int rep = 0; rep < 2; rep++) {
                    int idx = lane + rep * 32;
                    int kp = idx >> 3, m = idx & 7;
                    float2 vv = vb[kp], qq = qb[m];
                    float2 Qv = sQ[idx];
                    Qv.x -= vv.x * qq.x - vv.y * qq.y;
                    Qv.y -= vv.x * qq.y + vv.y * qq.x;
                    sQ[idx] = Qv;
                }
                __syncwarp();
            }
        }
    }
    __syncthreads();

    // ---- Qx = Q @ x ; xt = |Qx|^2 (unnormalized); local sum for scale ----
    float local = 0.f;
    float* out_xt = out + QELEMS + base;
    for (int i = tid; i < MDIM * TDIM; i += NTHREADS) {
        int m = i >> 9, t = i & 511;
        float ar = 0.f, ai = 0.f;
        #pragma unroll
        for (int n = 0; n < 8; n++) {
            float2 Qv = sQ[m * 8 + n];
            float xrv = sxr[n * XS + t];
            float xiv = sxi[n * XS + t];
            ar += Qv.x * xrv - Qv.y * xiv;
            ai += Qv.x * xiv + Qv.y * xrv;
        }
        float v = ar * ar + ai * ai;
        local += v;
        out_xt[i] = v;
    }
    // write unnormalized Q (real part only — output buffer is float32)
    if (tid < 64) {
        out[(size_t)bf * 64 + tid] = sQ[tid].x;
    }
    // deterministic fixed-order block reduction of `local`
    red[tid] = local;
    __syncthreads();
    for (int s = 144; s >= 9; s >>= 1) {
        if (tid < s) red[tid] += red[tid + s];
        __syncthreads();
    }
    if (tid == 0) {
        float s = 0.f;
        #pragma unroll
        for (int i = 0; i < 9; i++) s += red[i];
        g_partial[bf] = s;
    }
}

__global__ void iss_reduce()
{
    __shared__ float red[256];
    int b = blockIdx.x, tid = threadIdx.x;
    float s = 0.f;
    for (int i = tid; i < FDIM; i += 256) s += g_partial[b * FDIM + i];
    red[tid] = s;
    __syncthreads();
    for (int st = 128; st > 0; st >>= 1) {
        if (tid < st) red[tid] += red[tid + st];
        __syncthreads();
    }
    if (tid == 0) {
        float scale = red[0] / (float)PER_B_XT;
        g_xtscale[b] = 1.0f / scale;
        g_qscale[b]  = 1.0f / sqrtf(fmaxf(scale, 1e-6f));
    }
}

__global__ void iss_norm_xt(float* __restrict__ out)
{
    size_t idx = (size_t)blockIdx.x * blockDim.x + threadIdx.x;
    if (idx >= (size_t)XTCOUNT) return;
    int b = (int)(idx / PER_B_XT);
    out[QELEMS + idx] *= g_xtscale[b];
}

__global__ void iss_norm_q(float* __restrict__ out)
{
    int idx = blockIdx.x * blockDim.x + threadIdx.x;
    if (idx >= QELEMS) return;
    int b = idx / PER_B_QE;
    out[idx] *= g_qscale[b];
}

extern "C" void kernel_launch(void* const* d_in, const int* in_sizes, int n_in,
                              void* d_out, int out_size)
{
    const float* r  = (const float*)d_in[0];
    const float* Qr = (const float*)d_in[1];
    const float* Qi = (const float*)d_in[2];
    const float* xr = (const float*)d_in[3];
    const float* xi = (const float*)d_in[4];
    float* out = (float*)d_out;

    cudaFuncSetAttribute(iss_main, cudaFuncAttributeMaxDynamicSharedMemorySize, SMEM_BYTES);

    iss_main<<<NBF, NTHREADS, SMEM_BYTES>>>(r, Qr, Qi, xr, xi, out);
    iss_reduce<<<BDIM, 256>>>();
    iss_norm_xt<<<(XTCOUNT + 255) / 256, 256>>>(out);
    iss_norm_q<<<(QELEMS + 255) / 256, 256>>>(out);
}

// round 4
// speedup vs baseline: 1.3191x; 1.3191x over previous
#include <cuda_runtime.h>
#include <math.h>

#define BDIM 8
#define FDIM 1025
#define MDIM 8
#define TDIM 512
#define NBF (BDIM * FDIM)            // 8200
#define NTHREADS 288
#define XS 516                        // padded SMEM row stride (multiple of 4 -> 16B aligned rows)

#define QELEMS (NBF * MDIM * MDIM)           // 524,800  (Q stored as real part only)
#define XTCOUNT (NBF * MDIM * TDIM)          // 33,587,200
#define PER_B_XT (FDIM * MDIM * TDIM)        // 4,198,400
#define PER_B_QE (FDIM * MDIM * MDIM)        // 65,600

// SMEM layout (float offsets)
#define OFF_SXR 0
#define OFF_SXI (OFF_SXR + MDIM * XS)        // 4128
#define OFF_SR  (OFF_SXI + MDIM * XS)        // 8256
#define OFF_V   (OFF_SR + MDIM * XS)         // 12384  (512 float2)
#define OFF_PART (OFF_V + 1024)              // 13408  (2304 float2)
#define OFF_SQ  (OFF_PART + 4608)            // 18016  (64 float2)
#define OFF_QB  (OFF_SQ + 128)               // 18144  (8 float2)
#define OFF_VQ  (OFF_QB + 16)                // 18160  (64 float2)
#define OFF_VB  (OFF_VQ + 128)               // 18288  (8 float2)
#define OFF_RED (OFF_VB + 16)                // 18304  (288 float)
#define SMEM_FLOATS (OFF_RED + NTHREADS)
#define SMEM_BYTES (SMEM_FLOATS * 4)

typedef unsigned long long ull;
#define SGN2 0x8000000080000000ULL

__device__ __forceinline__ ull f2_pack(float lo, float hi) {
    ull r; asm("mov.b64 %0,{%1,%2};" : "=l"(r) : "f"(lo), "f"(hi)); return r;
}
__device__ __forceinline__ void f2_unpack(ull v, float& lo, float& hi) {
    asm("mov.b64 {%0,%1},%2;" : "=f"(lo), "=f"(hi) : "l"(v));
}
__device__ __forceinline__ ull f2_fma(ull a, ull b, ull c) {
    ull d; asm("fma.rn.f32x2 %0,%1,%2,%3;" : "=l"(d) : "l"(a), "l"(b), "l"(c)); return d;
}
__device__ __forceinline__ ull f2_mul(ull a, ull b) {
    ull d; asm("mul.rn.f32x2 %0,%1,%2;" : "=l"(d) : "l"(a), "l"(b)); return d;
}

__device__ float g_partial[NBF];
__device__ float g_xtscale[BDIM];
__device__ float g_qscale[BDIM];

__constant__ unsigned char c_pm[36] = {
    0,0,0,0,0,0,0,0,
    1,1,1,1,1,1,1,
    2,2,2,2,2,2,
    3,3,3,3,3,
    4,4,4,4,
    5,5,5,
    6,6,
    7};
__constant__ unsigned char c_pn[36] = {
    0,1,2,3,4,5,6,7,
    1,2,3,4,5,6,7,
    2,3,4,5,6,7,
    3,4,5,6,7,
    4,5,6,7,
    5,6,7,
    6,7,
    7};

__global__ __launch_bounds__(NTHREADS)
void iss_main(const float* __restrict__ r,
              const float* __restrict__ Qr,
              const float* __restrict__ Qi,
              const float* __restrict__ xr,
              const float* __restrict__ xi,
              float* __restrict__ out)
{
    extern __shared__ float sm[];
    float*  sxr  = sm + OFF_SXR;
    float*  sxi  = sm + OFF_SXI;
    float*  sr   = sm + OFF_SR;
    float2* V    = (float2*)(sm + OFF_V);     // [k][m][n]
    float2* part = (float2*)(sm + OFF_PART);  // [pair][k][chunk]
    float2* sQ   = (float2*)(sm + OFF_SQ);    // [k][m]
    float2* qb   = (float2*)(sm + OFF_QB);
    float2* Vq   = (float2*)(sm + OFF_VQ);
    float2* vb   = (float2*)(sm + OFF_VB);
    float*  red  = sm + OFF_RED;

    const int tid = threadIdx.x;
    const int bf = blockIdx.x;
    const size_t base = (size_t)bf * (MDIM * TDIM);

    // ---- stage inputs in SMEM via float4 (r clipped at load) ----
    {
        const float4* xr4 = (const float4*)(xr + base);
        const float4* xi4 = (const float4*)(xi + base);
        const float4* r4  = (const float4*)(r + base);
        for (int i = tid; i < MDIM * TDIM / 4; i += NTHREADS) {
            int m = i >> 7, t4 = (i & 127) << 2;
            float4 a = xr4[i];
            *(float4*)(sxr + m * XS + t4) = a;
            float4 b = xi4[i];
            *(float4*)(sxi + m * XS + t4) = b;
            float4 c = r4[i];
            c.x = fmaxf(c.x, 1e-3f); c.y = fmaxf(c.y, 1e-3f);
            c.z = fmaxf(c.z, 1e-3f); c.w = fmaxf(c.w, 1e-3f);
            *(float4*)(sr + m * XS + t4) = c;
        }
    }
    if (tid < 64) {
        sQ[tid] = make_float2(Qr[(size_t)bf * 64 + tid], Qi[(size_t)bf * 64 + tid]);
    }
    __syncthreads();

    // ---- V[k,m,n] = (1/T) sum_t clip(r)[k,t] * x[m,t] * conj(x[n,t]) ----
    // work item = (chunk of 64 t's) x (pair of 36 Hermitian (m,n))
    // accumulate packed over t-pairs with fma.rn.f32x2
    {
        int chunk = tid / 36;
        int pair  = tid - chunk * 36;
        int m = c_pm[pair], n = c_pn[pair];
        const ulonglong2* pxrm = (const ulonglong2*)(sxr + m * XS + chunk * 64);
        const ulonglong2* pxim = (const ulonglong2*)(sxi + m * XS + chunk * 64);
        const ulonglong2* pxrn = (const ulonglong2*)(sxr + n * XS + chunk * 64);
        const ulonglong2* pxin = (const ulonglong2*)(sxi + n * XS + chunk * 64);
        const float* srl = sr + chunk * 64;

        ull accx[8], accy[8];
        #pragma unroll
        for (int k = 0; k < 8; k++) { accx[k] = 0ULL; accy[k] = 0ULL; }

        #pragma unroll 2
        for (int q = 0; q < 16; q++) {            // q indexes groups of 4 t's
            ulonglong2 vrm = pxrm[q];
            ulonglong2 vim = pxim[q];
            ulonglong2 vrn = pxrn[q];
            ulonglong2 vin = pxin[q];
            // a = Re(x_m conj(x_n)), b = Im(x_m conj(x_n)), packed over t-pairs
            ull a01 = f2_fma(vrm.x, vrn.x, f2_mul(vim.x, vin.x));
            ull a23 = f2_fma(vrm.y, vrn.y, f2_mul(vim.y, vin.y));
            ull b01 = f2_fma(vim.x, vrn.x, f2_mul(vrm.x ^ SGN2, vin.x));
            ull b23 = f2_fma(vim.y, vrn.y, f2_mul(vrm.y ^ SGN2, vin.y));
            #pragma unroll
            for (int k = 0; k < 8; k++) {
                ulonglong2 rk = *(const ulonglong2*)(srl + k * XS + q * 4);
                accx[k] = f2_fma(rk.x, a01, accx[k]);
                accx[k] = f2_fma(rk.y, a23, accx[k]);
                accy[k] = f2_fma(rk.x, b01, accy[k]);
                accy[k] = f2_fma(rk.y, b23, accy[k]);
            }
        }
        #pragma unroll
        for (int k = 0; k < 8; k++) {
            float xl, xh, yl, yh;
            f2_unpack(accx[k], xl, xh);
            f2_unpack(accy[k], yl, yh);
            part[(pair * 8 + k) * 8 + chunk] = make_float2(xl + xh, yl + yh);
        }
    }
    __syncthreads();

    // reduce over chunks, Hermitian fill. 36*8 = 288 items exactly.
    {
        int pair = tid >> 3, k = tid & 7;
        int m = c_pm[pair], n = c_pn[pair];
        float2 s = make_float2(0.f, 0.f);
        #pragma unroll
        for (int c = 0; c < 8; c++) {
            float2 p = part[(pair * 8 + k) * 8 + c];
            s.x += p.x; s.y += p.y;
        }
        s.x *= (1.0f / TDIM);
        s.y *= (1.0f / TDIM);
        V[(k * 8 + m) * 8 + n] = s;
        V[(k * 8 + n) * 8 + m] = make_float2(s.x, -s.y);
    }
    __syncthreads();

    // trV + diagonal regularization
    if (tid < 8) {
        int k = tid;
        float tr = 0.f;
        #pragma unroll
        for (int m = 0; m < 8; m++) tr += V[(k * 8 + m) * 8 + m].x;
        float reg = fmaxf(tr, 1.0f) * 1e-6f;
        #pragma unroll
        for (int m = 0; m < 8; m++) V[(k * 8 + m) * 8 + m].x += reg;
    }
    __syncthreads();

    // ---- 2 x 8 sweep iteration, done by warp 0 ----
    if (tid < 32) {
        const int lane = tid;
        for (int it = 0; it < 2; it++) {
            for (int k = 0; k < 8; k++) {
                if (lane < 8) qb[lane] = sQ[k * 8 + lane];
                __syncwarp();
                // Vq[kp,m] = sum_n V[kp,m,n] * conj(q[n])
                #pragma unroll
                for (int rep = 0; rep < 2; rep++) {
                    int kp = (lane >> 3) + rep * 4;
                    int m  = lane & 7;
                    float sx = 0.f, sy = 0.f;
                    #pragma unroll
                    for (int n = 0; n < 8; n++) {
                        float2 vv = V[(kp * 8 + m) * 8 + n];
                        float2 qq = qb[n];
                        sx += vv.x * qq.x + vv.y * qq.y;
                        sy += vv.y * qq.x - vv.x * qq.y;
                    }
                    Vq[kp * 8 + m] = make_float2(sx, sy);
                }
                __syncwarp();
                if (lane < 8) {
                    int kp = lane;
                    float sreal = 0.f;
                    float2 num = make_float2(0.f, 0.f);
                    #pragma unroll
                    for (int m = 0; m < 8; m++) {
                        float2 qq  = qb[m];
                        float2 vqm = Vq[kp * 8 + m];
                        sreal += qq.x * vqm.x - qq.y * vqm.y;
                        float2 Qv = sQ[kp * 8 + m];
                        num.x += Qv.x * vqm.x - Qv.y * vqm.y;
                        num.y += Qv.x * vqm.y + Qv.y * vqm.x;
                    }
                    float qv = fmaxf(sreal, 1e-6f);
                    float2 vv;
                    if (kp == k) {
                        vv = make_float2(1.0f - 1.0f / sqrtf(qv), 0.0f);
                    } else {
                        vv = make_float2(num.x / qv, num.y / qv);
                    }
                    vb[kp] = vv;
                }
                __syncwarp();
                // Q[kp,m] -= v[kp] * q[m]
                #pragma unroll
                for (int rep = 0; rep < 2; rep++) {
                    int idx = lane + rep * 32;
                    int kp = idx >> 3, m = idx & 7;
                    float2 vv = vb[kp], qq = qb[m];
                    float2 Qv = sQ[idx];
                    Qv.x -= vv.x * qq.x - vv.y * qq.y;
                    Qv.y -= vv.x * qq.y + vv.y * qq.x;
                    sQ[idx] = Qv;
                }
                __syncwarp();
            }
        }
    }
    __syncthreads();

    // ---- Qx = Q @ x ; xt = |Qx|^2 (unnormalized); local sum for scale ----
    // threads 0..255: m = tid>>5 fixed per thread; Q packs hoisted to registers.
    float local = 0.f;
    float* out_xt = out + QELEMS + base;
    if (tid < 256) {
        int m = tid >> 5;
        int lane = tid & 31;
        ull Qxx2[8], Qyy2[8];
        #pragma unroll
        for (int n = 0; n < 8; n++) {
            float2 Qv = sQ[m * 8 + n];
            Qxx2[n] = f2_pack(Qv.x, Qv.x);
            Qyy2[n] = f2_pack(Qv.y, Qv.y);
        }
        #pragma unroll
        for (int j = 0; j < 4; j++) {
            int t = (lane + j * 32) * 4;    // 4 consecutive t's
            ull arA01 = 0, arA23 = 0;       // sum Qx*xr
            ull arB01 = 0, arB23 = 0;       // sum Qy*xi  (subtract at end)
            ull ai01 = 0, ai23 = 0;         // sum Qx*xi + Qy*xr
            #pragma unroll
            for (int n = 0; n < 8; n++) {
                ulonglong2 vr = *(const ulonglong2*)(sxr + n * XS + t);
                ulonglong2 vi = *(const ulonglong2*)(sxi + n * XS + t);
                arA01 = f2_fma(Qxx2[n], vr.x, arA01);
                arA23 = f2_fma(Qxx2[n], vr.y, arA23);
                arB01 = f2_fma(Qyy2[n], vi.x, arB01);
                arB23 = f2_fma(Qyy2[n], vi.y, arB23);
                ai01  = f2_fma(Qxx2[n], vi.x, ai01);
                ai23  = f2_fma(Qxx2[n], vi.y, ai23);
                ai01  = f2_fma(Qyy2[n], vr.x, ai01);
                ai23  = f2_fma(Qyy2[n], vr.y, ai23);
            }
            float a0,a1,a2,a3, b0,b1,b2,b3, i0,i1,i2,i3;
            f2_unpack(arA01, a0, a1); f2_unpack(arA23, a2, a3);
            f2_unpack(arB01, b0, b1); f2_unpack(arB23, b2, b3);
            f2_unpack(ai01,  i0, i1); f2_unpack(ai23,  i2, i3);
            float r0 = a0 - b0, r1 = a1 - b1, r2 = a2 - b2, r3 = a3 - b3;
            float4 v;
            v.x = r0 * r0 + i0 * i0;
            v.y = r1 * r1 + i1 * i1;
            v.z = r2 * r2 + i2 * i2;
            v.w = r3 * r3 + i3 * i3;
            local += v.x + v.y + v.z + v.w;
            *(float4*)(out_xt + m * TDIM + t) = v;
        }
    }
    // write unnormalized Q (real part only — output buffer is float32)
    if (tid < 64) {
        out[(size_t)bf * 64 + tid] = sQ[tid].x;
    }
    // deterministic fixed-order block reduction of `local`
    red[tid] = local;
    __syncthreads();
    for (int s = 144; s >= 9; s >>= 1) {
        if (tid < s) red[tid] += red[tid + s];
        __syncthreads();
    }
    if (tid == 0) {
        float s = 0.f;
        #pragma unroll
        for (int i = 0; i < 9; i++) s += red[i];
        g_partial[bf] = s;
    }
}

__global__ void iss_reduce()
{
    __shared__ float red[256];
    int b = blockIdx.x, tid = threadIdx.x;
    float s = 0.f;
    for (int i = tid; i < FDIM; i += 256) s += g_partial[b * FDIM + i];
    red[tid] = s;
    __syncthreads();
    for (int st = 128; st > 0; st >>= 1) {
        if (tid < st) red[tid] += red[tid + st];
        __syncthreads();
    }
    if (tid == 0) {
        float scale = red[0] / (float)PER_B_XT;
        g_xtscale[b] = 1.0f / scale;
        g_qscale[b]  = 1.0f / sqrtf(fmaxf(scale, 1e-6f));
    }
}

__global__ void iss_norm_xt(float4* __restrict__ outv)
{
    size_t idx = (size_t)blockIdx.x * blockDim.x + threadIdx.x;
    if (idx >= (size_t)(XTCOUNT / 4)) return;
    int b = (int)(idx / (PER_B_XT / 4));
    float s = g_xtscale[b];
    float4 v = outv[idx];
    v.x *= s; v.y *= s; v.z *= s; v.w *= s;
    outv[idx] = v;
}

__global__ void iss_norm_q(float* __restrict__ out)
{
    int idx = blockIdx.x * blockDim.x + threadIdx.x;
    if (idx >= QELEMS) return;
    int b = idx / PER_B_QE;
    out[idx] *= g_qscale[b];
}

extern "C" void kernel_launch(void* const* d_in, const int* in_sizes, int n_in,
                              void* d_out, int out_size)
{
    const float* r  = (const float*)d_in[0];
    const float* Qr = (const float*)d_in[1];
    const float* Qi = (const float*)d_in[2];
    const float* xr = (const float*)d_in[3];
    const float* xi = (const float*)d_in[4];
    float* out = (float*)d_out;

    cudaFuncSetAttribute(iss_main, cudaFuncAttributeMaxDynamicSharedMemorySize, SMEM_BYTES);

    iss_main<<<NBF, NTHREADS, SMEM_BYTES>>>(r, Qr, Qi, xr, xi, out);
    iss_reduce<<<BDIM, 256>>>();
    iss_norm_xt<<<(XTCOUNT / 4 + 255) / 256, 256>>>((float4*)(out + QELEMS));
    iss_norm_q<<<(QELEMS + 255) / 256, 256>>>(out);
}